// round 14
// baseline (speedup 1.0000x reference)
#include <cuda_runtime.h>
#include <cuda_fp16.h>
#include <cstdint>
#include <math.h>

// ----------------------------------------------------------------------------
// StackDevConv, factorized + dst-sorted edges + f16 mma + f16 A/B gather.
//   W1 = [Wa | Wb];  A[n] = x[n]@(Wa-Wb)^T + b1 ;  B[n] = x[n]@Wb^T
//     (computed fp32, stored f16)
//   per edge: h = relu(A[dst]+B[src]) in half2;  msg = h @ W2^T  (f16 mma)
//   out[n] = segment_max(msg, dst) + b2 at emit ; empty -> 0
// R13 ncu: scatter was a 16-deep serial LDS->FMAX chain (~500cyc/tile).
// R14: batch-load scatter (float2 x 2 cols, 128 threads; warps 4-7 skip ahead),
// bias-after-max (monotone-equivalent), empty-node bitmask init (drops the
// finalize launch + finite_fix path).
// ----------------------------------------------------------------------------

#define DIMV    64
#define TPB     256
#define PADW    68
#define E_TILE  64
#define MAX_NODES 50000
#define MAX_EDGES 800000

#define SHH 36                    // sH stride in 32-bit words (64 halves + pad)
#define SMS 72                    // sMsg stride (float)
#define SHH_WORDS (64*SHH)        // 2304
#define SMS_WORDS (64*SMS)        // 4608

__device__ float        g_h1[MAX_NODES * DIMV];
__device__ unsigned int g_A [MAX_NODES * 32];   // 64 halves/node
__device__ unsigned int g_B [MAX_NODES * 32];
__device__ int   g_count [MAX_NODES];
__device__ int   g_offset[MAX_NODES];
__device__ int   g_empty [MAX_NODES];
__device__ int   g_src_s[MAX_EDGES];
__device__ int   g_dst_s[MAX_EDGES];

#define PRE_SMEM_FLOATS (64*PADW*3 + 64)
#define PRE_SMEM_BYTES  (PRE_SMEM_FLOATS*4)

// edge smem: sH[2 x 2304] + sMsg[2 x 4608] + sDst[4][64]
#define EDGE_SMEM_WORDS (2*SHH_WORDS + 2*SMS_WORDS + 4*64)
#define EDGE_SMEM_BYTES (EDGE_SMEM_WORDS*4)

__device__ __forceinline__ void atomic_max_float(float* addr, float value) {
    unsigned int ui = __float_as_uint(value);
    if ((int)ui >= 0) atomicMax((int*)addr, (int)ui);
    else              atomicMin((unsigned int*)addr, ui);
}

__device__ __forceinline__ unsigned int pkh2(float lo, float hi) {
    __half2 h = __float22half2_rn(make_float2(lo, hi));
    return *reinterpret_cast<unsigned int*>(&h);
}

__device__ __forceinline__ unsigned int haddrelu2(unsigned int a, unsigned int b) {
    __half2 r = __hmax2(__hadd2(*reinterpret_cast<__half2*>(&a),
                                *reinterpret_cast<__half2*>(&b)),
                        __half2(__half(0.0f), __half(0.0f)));
    return *reinterpret_cast<unsigned int*>(&r);
}

__device__ __forceinline__ void ldsm_x4(unsigned &r0, unsigned &r1,
                                        unsigned &r2, unsigned &r3,
                                        unsigned addr) {
    asm volatile("ldmatrix.sync.aligned.m8n8.x4.shared.b16 {%0,%1,%2,%3}, [%4];"
                 : "=r"(r0), "=r"(r1), "=r"(r2), "=r"(r3) : "r"(addr));
}

// ---------------- counting sort by dst ----------------
__global__ void hist_kernel(const int* __restrict__ dst, int n_edges) {
    int i = blockIdx.x * blockDim.x + threadIdx.x;
    if (i < n_edges) atomicAdd(&g_count[dst[i]], 1);
}

// exclusive scan of g_count -> g_offset; records empty nodes; re-zeros counts.
__global__ void scan_zero_kernel(int n_nodes) {
    __shared__ int partial[1024];
    const int tid = threadIdx.x;
    const int chunk = (n_nodes + 1023) / 1024;
    const int begin = tid * chunk;
    const int end   = min(begin + chunk, n_nodes);
    int s = 0;
    for (int i = begin; i < end; i++) s += g_count[i];
    partial[tid] = s;
    __syncthreads();
    for (int off = 1; off < 1024; off <<= 1) {
        int v = partial[tid];
        int add = (tid >= off) ? partial[tid - off] : 0;
        __syncthreads();
        partial[tid] = v + add;
        __syncthreads();
    }
    int base = (tid > 0) ? partial[tid - 1] : 0;
    for (int i = begin; i < end; i++) {
        const int c = g_count[i];
        g_offset[i] = base;
        base += c;
        g_empty[i] = (c == 0);
        g_count[i] = 0;
    }
}

// ---------------- per-node precompute body (fp32 math, f16 store) ----------------
__device__ __forceinline__
void pre_body(float* smem, int n0,
              const float* __restrict__ x,
              const float* __restrict__ W1, const float* __restrict__ b1,
              unsigned int* __restrict__ Ah, unsigned int* __restrict__ Bh,
              int n_nodes, int tid)
{
    float* sWdT = smem;
    float* sWbT = sWdT + 64 * PADW;
    float* sB1  = sWbT + 64 * PADW;
    float* sXT  = sB1 + 64;

    for (int i = tid; i < 64 * 64; i += TPB) {
        int c = i >> 6, k = i & 63;
        float wa = W1[c * 128 + k];
        float wb = W1[c * 128 + 64 + k];
        sWdT[k * PADW + c] = wa - wb;
        sWbT[k * PADW + c] = wb;
    }
    if (tid < 64) sB1[tid] = b1[tid];

    {
        const int e = tid >> 2;
        const int q = tid & 3;
        const int node = n0 + e;
        const float4* xr = (const float4*)(x + (size_t)(node < n_nodes ? node : 0) * DIMV);
        #pragma unroll
        for (int v = 0; v < 4; v++) {
            const int c4 = q * 4 + v;
            float4 a = (node < n_nodes) ? xr[c4] : make_float4(0.f,0.f,0.f,0.f);
            const int c = c4 * 4;
            sXT[(c + 0) * PADW + e] = a.x;
            sXT[(c + 1) * PADW + e] = a.y;
            sXT[(c + 2) * PADW + e] = a.z;
            sXT[(c + 3) * PADW + e] = a.w;
        }
    }
    __syncthreads();

    const int ty = tid >> 4, tx = tid & 15;
    const int r = ty * 4, cc = tx * 4;

    float accA[4][4], accB[4][4];
    #pragma unroll
    for (int i = 0; i < 4; i++)
        #pragma unroll
        for (int j = 0; j < 4; j++) { accA[i][j] = sB1[cc + j]; accB[i][j] = 0.f; }

    #pragma unroll 2
    for (int k = 0; k < 64; k++) {
        const float4 xf = *(const float4*)&sXT[k * PADW + r];
        const float4 wd = *(const float4*)&sWdT[k * PADW + cc];
        const float4 wb = *(const float4*)&sWbT[k * PADW + cc];
        const float a0 = xf.x, a1 = xf.y, a2 = xf.z, a3 = xf.w;
        accA[0][0]+=a0*wd.x; accA[0][1]+=a0*wd.y; accA[0][2]+=a0*wd.z; accA[0][3]+=a0*wd.w;
        accA[1][0]+=a1*wd.x; accA[1][1]+=a1*wd.y; accA[1][2]+=a1*wd.z; accA[1][3]+=a1*wd.w;
        accA[2][0]+=a2*wd.x; accA[2][1]+=a2*wd.y; accA[2][2]+=a2*wd.z; accA[2][3]+=a2*wd.w;
        accA[3][0]+=a3*wd.x; accA[3][1]+=a3*wd.y; accA[3][2]+=a3*wd.z; accA[3][3]+=a3*wd.w;
        accB[0][0]+=a0*wb.x; accB[0][1]+=a0*wb.y; accB[0][2]+=a0*wb.z; accB[0][3]+=a0*wb.w;
        accB[1][0]+=a1*wb.x; accB[1][1]+=a1*wb.y; accB[1][2]+=a1*wb.z; accB[1][3]+=a1*wb.w;
        accB[2][0]+=a2*wb.x; accB[2][1]+=a2*wb.y; accB[2][2]+=a2*wb.z; accB[2][3]+=a2*wb.w;
        accB[3][0]+=a3*wb.x; accB[3][1]+=a3*wb.y; accB[3][2]+=a3*wb.z; accB[3][3]+=a3*wb.w;
    }

    #pragma unroll
    for (int i = 0; i < 4; i++) {
        const int node = n0 + r + i;
        if (node < n_nodes) {
            *(uint2*)&Ah[(size_t)node * 32 + (cc >> 1)] =
                make_uint2(pkh2(accA[i][0], accA[i][1]), pkh2(accA[i][2], accA[i][3]));
            *(uint2*)&Bh[(size_t)node * 32 + (cc >> 1)] =
                make_uint2(pkh2(accB[i][0], accB[i][1]), pkh2(accB[i][2], accB[i][3]));
        }
    }
}

// ---------------- fused scatter + init + pre (block-range dispatch) ----------------
// init uses g_empty: empty nodes -> 0.0 (final value), others -> -inf (atomics
// will overwrite every column). nblk_scatter=0 reuses this for layer 2.
__global__ __launch_bounds__(TPB, 3)
void fused_spi_kernel(const int* __restrict__ src, const int* __restrict__ dst,
                      int n_edges,
                      const float* __restrict__ x,
                      const float* __restrict__ W1, const float* __restrict__ b1,
                      unsigned int* __restrict__ Ah, unsigned int* __restrict__ Bh,
                      int n_nodes,
                      float* __restrict__ init_buf, int n_feat,
                      int nblk_scatter, int nblk_init)
{
    extern __shared__ float fsm[];
    const int b = blockIdx.x;
    if (b < nblk_scatter) {
        int i = b * TPB + threadIdx.x;
        if (i < n_edges) {
            int d = dst[i];
            int pos = atomicAdd(&g_offset[d], 1);
            g_src_s[pos] = src[i];
            g_dst_s[pos] = d;
        }
    } else if (b < nblk_scatter + nblk_init) {
        int i = (b - nblk_scatter) * TPB + threadIdx.x;
        if (i < n_feat) {
            const int node = i >> 6;
            ((unsigned int*)init_buf)[i] = g_empty[node] ? 0u : 0xFF800000u;
        }
    } else {
        pre_body(fsm, (b - nblk_scatter - nblk_init) * 64,
                 x, W1, b1, Ah, Bh, n_nodes, threadIdx.x);
    }
}

// ---------------- edge kernel: f16 mma + batch-load scatter ----------------
__global__ __launch_bounds__(TPB, 2)
void edge_kernel(const unsigned int* __restrict__ Ah,
                 const unsigned int* __restrict__ Bh,
                 const float* __restrict__ W2, const float* __restrict__ b2,
                 float* __restrict__ out, int n_edges, int tiles_per_block)
{
    extern __shared__ unsigned int usmem[];
    unsigned int* sHb   = usmem;                               // 2 x [64][SHH]
    float*        sMsgb = (float*)(usmem + 2 * SHH_WORDS);     // 2 x [64][SMS]
    int*          sDstb = (int*)(usmem + 2 * SHH_WORDS + 2 * SMS_WORDS); // 4 x [64]

    const int tid  = threadIdx.x;
    const int wid  = tid >> 5;
    const int lane = tid & 31;
    const int grp  = lane >> 2;
    const int qd   = lane & 3;

    const int m0  = (wid >> 1) * 16;   // warp's edge-group base
    const int n0w = (wid & 1) * 32;    // warp's column half

    // ---- W2 f16 fragments -> registers, ONCE (m16n8k16 B layout) ----
    uint2 wB[4][4];
    #pragma unroll
    for (int nt = 0; nt < 4; nt++) {
        const int row = n0w + nt * 8 + grp;
        #pragma unroll
        for (int ks = 0; ks < 4; ks++) {
            const int k0 = ks * 16 + 2 * qd;
            wB[nt][ks] = make_uint2(
                pkh2(W2[row * 64 + k0    ], W2[row * 64 + k0 + 1]),
                pkh2(W2[row * 64 + k0 + 8], W2[row * 64 + k0 + 9]));
        }
    }

    const int e = tid >> 2, q = tid & 3;        // gather role: 4 threads/edge

    // scatter role: tid<128; warp = chain of 16 edges, lane = col pair
    const int chS = tid >> 5;          // 0..3 for tid<128
    const int c2S = (tid & 31) * 2;
    const int r2S = chS * 16;
    float2 bv = make_float2(0.f, 0.f);
    if (tid < 128) bv = *(const float2*)&b2[c2S];

    const int n_tiles = (n_edges + E_TILE - 1) / E_TILE;
    const int t0 = blockIdx.x * tiles_per_block;
    const int t1 = min(t0 + tiles_per_block, n_tiles);
    if (t0 >= t1) return;   // block-uniform

    unsigned int sbase;
    asm("{ .reg .u64 t; cvta.to.shared.u64 t, %1; cvt.u32.u64 %0, t; }"
        : "=r"(sbase) : "l"((void*)usmem));
    const unsigned int lds_off =
        ((unsigned)((m0 + (lane & 15)) * SHH + (lane >> 4) * 4)) * 4u;

    // ---- prologue: full gather of tile t0 -> sH buf0, sDst[t0&3] ----
    {
        const int eg = t0 * E_TILE + e;
        const bool valid = (eg < n_edges);
        int s = 0, d = -1;
        if (valid) { s = g_src_s[eg]; d = g_dst_s[eg]; }
        const uint4* a4 = (const uint4*)(Ah + (size_t)(valid ? d : 0) * 32) + q * 2;
        const uint4* b4 = (const uint4*)(Bh + (size_t)s * 32) + q * 2;
        uint4* hp = (uint4*)((char*)sHb + e * (SHH * 4) + q * 32);
        if (q == 0) sDstb[(t0 & 3) * 64 + e] = d;
        #pragma unroll
        for (int v = 0; v < 2; v++) {
            uint4 a = valid ? a4[v] : make_uint4(0,0,0,0);
            uint4 b = valid ? b4[v] : make_uint4(0,0,0,0);
            uint4 hv;
            hv.x = haddrelu2(a.x, b.x);
            hv.y = haddrelu2(a.y, b.y);
            hv.z = haddrelu2(a.z, b.z);
            hv.w = haddrelu2(a.w, b.w);
            hp[v] = hv;
        }
    }
    __syncthreads();

    int p = 0;
    for (int t = t0; t < t1; t++, p ^= 1) {
        // ---- 1. prefetch next tile's random B[src] (issues before mma) ----
        const int tn = t + 1;
        const int egN = tn * E_TILE + e;
        const bool validN = (tn < t1) && (egN < n_edges);
        int sN = 0, dN = -1;
        if (validN) { sN = g_src_s[egN]; dN = g_dst_s[egN]; }
        uint4 bb[2];
        {
            const uint4* b4 = (const uint4*)(Bh + (size_t)sN * 32) + q * 2;
            #pragma unroll
            for (int v = 0; v < 2; v++)
                bb[v] = validN ? b4[v] : make_uint4(0,0,0,0);
        }

        // ---- 2. f16 mma from sH[p] via ldmatrix, W2 frags in regs ----
        float acc[4][4];
        #pragma unroll
        for (int nt = 0; nt < 4; nt++)
            #pragma unroll
            for (int j = 0; j < 4; j++) acc[nt][j] = 0.f;

        const unsigned int abase = sbase + (unsigned)p * (SHH_WORDS * 4u) + lds_off;
        #pragma unroll
        for (int ks = 0; ks < 4; ks++) {
            unsigned int a0, a1, a2, a3;
            ldsm_x4(a0, a1, a2, a3, abase + ks * 32u);
            #pragma unroll
            for (int nt = 0; nt < 4; nt++) {
                asm volatile(
                    "mma.sync.aligned.m16n8k16.row.col.f32.f16.f16.f32 "
                    "{%0,%1,%2,%3}, {%4,%5,%6,%7}, {%8,%9}, {%0,%1,%2,%3};"
                    : "+f"(acc[nt][0]), "+f"(acc[nt][1]),
                      "+f"(acc[nt][2]), "+f"(acc[nt][3])
                    : "r"(a0), "r"(a1), "r"(a2), "r"(a3),
                      "r"(wB[nt][ks].x), "r"(wB[nt][ks].y));
            }
        }

        // ---- 3. finish next-tile gather: A row (cache-hot) + fuse + STS ----
        {
            const uint4* a4 = (const uint4*)(Ah + (size_t)(validN ? dN : 0) * 32) + q * 2;
            uint4* hp = (uint4*)((char*)sHb + (p ^ 1) * (SHH_WORDS * 4)
                                 + e * (SHH * 4) + q * 32);
            if (q == 0) sDstb[(tn & 3) * 64 + e] = dN;
            #pragma unroll
            for (int v = 0; v < 2; v++) {
                uint4 a = validN ? a4[v] : make_uint4(0,0,0,0);
                uint4 hv;
                hv.x = haddrelu2(a.x, bb[v].x);
                hv.y = haddrelu2(a.y, bb[v].y);
                hv.z = haddrelu2(a.z, bb[v].z);
                hv.w = haddrelu2(a.w, bb[v].w);
                hp[v] = hv;
            }
        }

        // ---- 4. write raw acc to sMsg[p] (bias added at emit) ----
        float* msg = sMsgb + p * SMS_WORDS;
        #pragma unroll
        for (int nt = 0; nt < 4; nt++) {
            const int c2 = n0w + nt * 8 + 2 * qd;
            *(float2*)&msg[(m0 + grp    ) * SMS + c2] = make_float2(acc[nt][0], acc[nt][1]);
            *(float2*)&msg[(m0 + grp + 8) * SMS + c2] = make_float2(acc[nt][2], acc[nt][3]);
        }
        __syncthreads();   // the ONE barrier: sMsg[p], sH[p^1], sDst ready

        // ---- 5. scatter (tid<128): batch-load, run-merge, bias at emit ----
        // Warps 4-7 skip straight to the next tile's prefetch.
        if (tid < 128) {
            const int* sd = sDstb + (t & 3) * 64;
            int rd[16];
            #pragma unroll
            for (int i4 = 0; i4 < 4; i4++)
                *(int4*)&rd[i4 * 4] = *(const int4*)&sd[r2S + i4 * 4];

            float2 cur = make_float2(0.f, 0.f);
            int prev = -2;
            #pragma unroll
            for (int h = 0; h < 2; h++) {
                float2 mv[8];
                #pragma unroll
                for (int j = 0; j < 8; j++)
                    mv[j] = *(const float2*)&msg[(r2S + h * 8 + j) * SMS + c2S];
                #pragma unroll
                for (int j = 0; j < 8; j++) {
                    const int g = h * 8 + j;
                    const int de = rd[g];
                    cur = (de == prev)
                        ? make_float2(fmaxf(cur.x, mv[j].x), fmaxf(cur.y, mv[j].y))
                        : mv[j];
                    prev = de;
                    const bool last = (g == 15) || (rd[g + 1] != de);
                    if (last && de >= 0) {
                        float* op = out + (size_t)de * DIMV + c2S;
                        atomic_max_float(op    , cur.x + bv.x);
                        atomic_max_float(op + 1, cur.y + bv.y);
                    }
                }
            }
        }
        // no trailing barrier (verified buffer rotation; sH[p]/sMsg[p^1]/
        // sDst[(t+2)&3] written next iter are disjoint from this window's reads).
    }
}

extern "C" void kernel_launch(void* const* d_in, const int* in_sizes, int n_in,
                              void* d_out, int out_size)
{
    const float* x   = (const float*)d_in[0];
    const int*   ei  = (const int*)d_in[1];
    const float* W1a = (const float*)d_in[2];
    const float* b1a = (const float*)d_in[3];
    const float* W2a = (const float*)d_in[4];
    const float* b2a = (const float*)d_in[5];
    const float* W1b = (const float*)d_in[6];
    const float* b1b = (const float*)d_in[7];
    const float* W2b = (const float*)d_in[8];
    const float* b2b = (const float*)d_in[9];

    const int n_nodes = in_sizes[0] / DIMV;
    const int n_edges = in_sizes[1] / 2;
    const int* src = ei;
    const int* dst = ei + n_edges;

    float* out = (float*)d_out;
    float* h1;
    unsigned int *Abuf, *Bbuf;
    cudaGetSymbolAddress((void**)&h1,   g_h1);
    cudaGetSymbolAddress((void**)&Abuf, g_A);
    cudaGetSymbolAddress((void**)&Bbuf, g_B);

    cudaFuncSetAttribute(fused_spi_kernel,
                         cudaFuncAttributeMaxDynamicSharedMemorySize, PRE_SMEM_BYTES);
    cudaFuncSetAttribute(edge_kernel,
                         cudaFuncAttributeMaxDynamicSharedMemorySize, EDGE_SMEM_BYTES);

    const int n_feat = n_nodes * DIMV;
    const int init_blocks = (n_feat + TPB - 1) / TPB;
    const int pre_blocks  = (n_nodes + 63) / 64;
    const int edge_blocks = 148 * 2;
    const int eb = (n_edges + TPB - 1) / TPB;

    const int n_tiles = (n_edges + E_TILE - 1) / E_TILE;
    const int tiles_per_block = (n_tiles + edge_blocks - 1) / edge_blocks;

    // #1 histogram (g_count zeroed by previous scan / initial BSS)
    hist_kernel<<<eb, TPB>>>(dst, n_edges);
    // #2 exclusive scan + empty bitmask + re-zero counts
    scan_zero_kernel<<<1, 1024>>>(n_nodes);
    // #3 fused: scatter-sort + init(h1, bitmask) + pre(layer1)
    fused_spi_kernel<<<eb + init_blocks + pre_blocks, TPB, PRE_SMEM_BYTES>>>(
        src, dst, n_edges, x, W1a, b1a, Abuf, Bbuf, n_nodes,
        h1, n_feat, eb, init_blocks);
    // #4 edge layer 1  <-- ncu captures this launch
    edge_kernel<<<edge_blocks, TPB, EDGE_SMEM_BYTES>>>(Abuf, Bbuf, W2a, b2a,
                                                       h1, n_edges, tiles_per_block);
    // #5 fused: init(out, bitmask) + pre(layer2)
    fused_spi_kernel<<<init_blocks + pre_blocks, TPB, PRE_SMEM_BYTES>>>(
        src, dst, n_edges, h1, W1b, b1b, Abuf, Bbuf, n_nodes,
        out, n_feat, 0, init_blocks);
    // #6 edge layer 2
    edge_kernel<<<edge_blocks, TPB, EDGE_SMEM_BYTES>>>(Abuf, Bbuf, W2b, b2b,
                                                       out, n_edges, tiles_per_block);
}

// round 17
// speedup vs baseline: 1.0409x; 1.0409x over previous
#include <cuda_runtime.h>
#include <cuda_fp16.h>
#include <cstdint>
#include <math.h>

// ----------------------------------------------------------------------------
// StackDevConv, factorized + dst-sorted edges + f16 mma + f16 everything.
//   W1 = [Wa | Wb];  A[n] = x[n]@(Wa-Wb)^T + b1 ;  B[n] = x[n]@Wb^T
//     (computed fp32, stored f16)
//   per edge: h = relu(A[dst]+B[src]) (half2);  msg = h @ W2^T (f16 mma),
//   stored f16;  out[n] = segment_max(msg) + b2 at emit ; empty -> 0
// R14: edge 89us/layer, issue 22%, occ 25% -> per-tile serial overhead paid
// 12500x. R15/16/17: E_TILE 128 (half the barriers/iters) enabled by f16 sMsg
// (monotone rounding before max -> same winner), still occ-2. Longer chains
// (32 sorted edges) cut atomics ~40%; max runs as packed __hmax2.
// (R15/R16 benches were broker infra failures - same error string as the
// empty-stub R0 run; kernel audited twice incl. deadlock-class checks.)
// ----------------------------------------------------------------------------

#define DIMV    64
#define TPB     256
#define PADW    68
#define E_TILE  128
#define MAX_NODES 50000
#define MAX_EDGES 800000

#define SHH 36                    // sH row stride in 32-bit words (64 halves+pad)
#define SMH 36                    // sMsg(f16) row stride in 32-bit words
#define SHH_WORDS (128*SHH)       // 4608 per buffer
#define SMH_WORDS (128*SMH)       // 4608 per buffer

__device__ float        g_h1[MAX_NODES * DIMV];
__device__ unsigned int g_A [MAX_NODES * 32];   // 64 halves/node
__device__ unsigned int g_B [MAX_NODES * 32];
__device__ int   g_count [MAX_NODES];
__device__ int   g_offset[MAX_NODES];
__device__ int   g_empty [MAX_NODES];
__device__ int   g_src_s[MAX_EDGES];
__device__ int   g_dst_s[MAX_EDGES];

#define PRE_SMEM_FLOATS (64*PADW*3 + 64)
#define PRE_SMEM_BYTES  (PRE_SMEM_FLOATS*4)

// edge smem: sH[2 x 4608] + sMsg[2 x 4608] + sDst[4][128]
#define EDGE_SMEM_WORDS (2*SHH_WORDS + 2*SMH_WORDS + 4*128)
#define EDGE_SMEM_BYTES (EDGE_SMEM_WORDS*4)

__device__ __forceinline__ void atomic_max_float(float* addr, float value) {
    unsigned int ui = __float_as_uint(value);
    if ((int)ui >= 0) atomicMax((int*)addr, (int)ui);
    else              atomicMin((unsigned int*)addr, ui);
}

__device__ __forceinline__ unsigned int pkh2(float lo, float hi) {
    __half2 h = __float22half2_rn(make_float2(lo, hi));
    return *reinterpret_cast<unsigned int*>(&h);
}

__device__ __forceinline__ unsigned int haddrelu2(unsigned int a, unsigned int b) {
    __half2 r = __hmax2(__hadd2(*reinterpret_cast<__half2*>(&a),
                                *reinterpret_cast<__half2*>(&b)),
                        __half2(__half(0.0f), __half(0.0f)));
    return *reinterpret_cast<unsigned int*>(&r);
}

__device__ __forceinline__ unsigned int hmax2w(unsigned int a, unsigned int b) {
    __half2 r = __hmax2(*reinterpret_cast<__half2*>(&a),
                        *reinterpret_cast<__half2*>(&b));
    return *reinterpret_cast<unsigned int*>(&r);
}

__device__ __forceinline__ void ldsm_x4(unsigned &r0, unsigned &r1,
                                        unsigned &r2, unsigned &r3,
                                        unsigned addr) {
    asm volatile("ldmatrix.sync.aligned.m8n8.x4.shared.b16 {%0,%1,%2,%3}, [%4];"
                 : "=r"(r0), "=r"(r1), "=r"(r2), "=r"(r3) : "r"(addr));
}

// ---------------- counting sort by dst ----------------
__global__ void hist_kernel(const int* __restrict__ dst, int n_edges) {
    int i = blockIdx.x * blockDim.x + threadIdx.x;
    if (i < n_edges) atomicAdd(&g_count[dst[i]], 1);
}

__global__ void scan_zero_kernel(int n_nodes) {
    __shared__ int partial[1024];
    const int tid = threadIdx.x;
    const int chunk = (n_nodes + 1023) / 1024;
    const int begin = tid * chunk;
    const int end   = min(begin + chunk, n_nodes);
    int s = 0;
    for (int i = begin; i < end; i++) s += g_count[i];
    partial[tid] = s;
    __syncthreads();
    for (int off = 1; off < 1024; off <<= 1) {
        int v = partial[tid];
        int add = (tid >= off) ? partial[tid - off] : 0;
        __syncthreads();
        partial[tid] = v + add;
        __syncthreads();
    }
    int base = (tid > 0) ? partial[tid - 1] : 0;
    for (int i = begin; i < end; i++) {
        const int c = g_count[i];
        g_offset[i] = base;
        base += c;
        g_empty[i] = (c == 0);
        g_count[i] = 0;
    }
}

// ---------------- per-node precompute body (fp32 math, f16 store) ----------------
__device__ __forceinline__
void pre_body(float* smem, int n0,
              const float* __restrict__ x,
              const float* __restrict__ W1, const float* __restrict__ b1,
              unsigned int* __restrict__ Ah, unsigned int* __restrict__ Bh,
              int n_nodes, int tid)
{
    float* sWdT = smem;
    float* sWbT = sWdT + 64 * PADW;
    float* sB1  = sWbT + 64 * PADW;
    float* sXT  = sB1 + 64;

    for (int i = tid; i < 64 * 64; i += TPB) {
        int c = i >> 6, k = i & 63;
        float wa = W1[c * 128 + k];
        float wb = W1[c * 128 + 64 + k];
        sWdT[k * PADW + c] = wa - wb;
        sWbT[k * PADW + c] = wb;
    }
    if (tid < 64) sB1[tid] = b1[tid];

    {
        const int e = tid >> 2;
        const int q = tid & 3;
        const int node = n0 + e;
        const float4* xr = (const float4*)(x + (size_t)(node < n_nodes ? node : 0) * DIMV);
        #pragma unroll
        for (int v = 0; v < 4; v++) {
            const int c4 = q * 4 + v;
            float4 a = (node < n_nodes) ? xr[c4] : make_float4(0.f,0.f,0.f,0.f);
            const int c = c4 * 4;
            sXT[(c + 0) * PADW + e] = a.x;
            sXT[(c + 1) * PADW + e] = a.y;
            sXT[(c + 2) * PADW + e] = a.z;
            sXT[(c + 3) * PADW + e] = a.w;
        }
    }
    __syncthreads();

    const int ty = tid >> 4, tx = tid & 15;
    const int r = ty * 4, cc = tx * 4;

    float accA[4][4], accB[4][4];
    #pragma unroll
    for (int i = 0; i < 4; i++)
        #pragma unroll
        for (int j = 0; j < 4; j++) { accA[i][j] = sB1[cc + j]; accB[i][j] = 0.f; }

    #pragma unroll 2
    for (int k = 0; k < 64; k++) {
        const float4 xf = *(const float4*)&sXT[k * PADW + r];
        const float4 wd = *(const float4*)&sWdT[k * PADW + cc];
        const float4 wb = *(const float4*)&sWbT[k * PADW + cc];
        const float a0 = xf.x, a1 = xf.y, a2 = xf.z, a3 = xf.w;
        accA[0][0]+=a0*wd.x; accA[0][1]+=a0*wd.y; accA[0][2]+=a0*wd.z; accA[0][3]+=a0*wd.w;
        accA[1][0]+=a1*wd.x; accA[1][1]+=a1*wd.y; accA[1][2]+=a1*wd.z; accA[1][3]+=a1*wd.w;
        accA[2][0]+=a2*wd.x; accA[2][1]+=a2*wd.y; accA[2][2]+=a2*wd.z; accA[2][3]+=a2*wd.w;
        accA[3][0]+=a3*wd.x; accA[3][1]+=a3*wd.y; accA[3][2]+=a3*wd.z; accA[3][3]+=a3*wd.w;
        accB[0][0]+=a0*wb.x; accB[0][1]+=a0*wb.y; accB[0][2]+=a0*wb.z; accB[0][3]+=a0*wb.w;
        accB[1][0]+=a1*wb.x; accB[1][1]+=a1*wb.y; accB[1][2]+=a1*wb.z; accB[1][3]+=a1*wb.w;
        accB[2][0]+=a2*wb.x; accB[2][1]+=a2*wb.y; accB[2][2]+=a2*wb.z; accB[2][3]+=a2*wb.w;
        accB[3][0]+=a3*wb.x; accB[3][1]+=a3*wb.y; accB[3][2]+=a3*wb.z; accB[3][3]+=a3*wb.w;
    }

    #pragma unroll
    for (int i = 0; i < 4; i++) {
        const int node = n0 + r + i;
        if (node < n_nodes) {
            *(uint2*)&Ah[(size_t)node * 32 + (cc >> 1)] =
                make_uint2(pkh2(accA[i][0], accA[i][1]), pkh2(accA[i][2], accA[i][3]));
            *(uint2*)&Bh[(size_t)node * 32 + (cc >> 1)] =
                make_uint2(pkh2(accB[i][0], accB[i][1]), pkh2(accB[i][2], accB[i][3]));
        }
    }
}

// ---------------- fused scatter + init + pre (block-range dispatch) ----------------
__global__ __launch_bounds__(TPB, 3)
void fused_spi_kernel(const int* __restrict__ src, const int* __restrict__ dst,
                      int n_edges,
                      const float* __restrict__ x,
                      const float* __restrict__ W1, const float* __restrict__ b1,
                      unsigned int* __restrict__ Ah, unsigned int* __restrict__ Bh,
                      int n_nodes,
                      float* __restrict__ init_buf, int n_feat,
                      int nblk_scatter, int nblk_init)
{
    extern __shared__ float fsm[];
    const int b = blockIdx.x;
    if (b < nblk_scatter) {
        int i = b * TPB + threadIdx.x;
        if (i < n_edges) {
            int d = dst[i];
            int pos = atomicAdd(&g_offset[d], 1);
            g_src_s[pos] = src[i];
            g_dst_s[pos] = d;
        }
    } else if (b < nblk_scatter + nblk_init) {
        int i = (b - nblk_scatter) * TPB + threadIdx.x;
        if (i < n_feat) {
            const int node = i >> 6;
            ((unsigned int*)init_buf)[i] = g_empty[node] ? 0u : 0xFF800000u;
        }
    } else {
        pre_body(fsm, (b - nblk_scatter - nblk_init) * 64,
                 x, W1, b1, Ah, Bh, n_nodes, threadIdx.x);
    }
}

// ---------------- edge kernel: 128-edge tiles, f16 end-to-end ----------------
__global__ __launch_bounds__(TPB, 2)
void edge_kernel(const unsigned int* __restrict__ Ah,
                 const unsigned int* __restrict__ Bh,
                 const float* __restrict__ W2, const float* __restrict__ b2,
                 float* __restrict__ out, int n_edges, int tiles_per_block)
{
    extern __shared__ unsigned int usmem[];
    unsigned int* sHb   = usmem;                              // 2 x [128][SHH]
    unsigned int* sMsgb = usmem + 2 * SHH_WORDS;              // 2 x [128][SMH] f16
    int*          sDstb = (int*)(usmem + 2 * SHH_WORDS + 2 * SMH_WORDS); // 4 x [128]

    const int tid  = threadIdx.x;
    const int wid  = tid >> 5;
    const int lane = tid & 31;
    const int grp  = lane >> 2;
    const int qd   = lane & 3;

    const int m0  = (wid >> 1) * 32;   // warp's 32-edge base (4 groups of 32)
    const int n0w = (wid & 1) * 32;    // warp's column half

    // ---- W2 f16 fragments -> registers, ONCE (m16n8k16 B layout) ----
    uint2 wB[4][4];
    #pragma unroll
    for (int nt = 0; nt < 4; nt++) {
        const int row = n0w + nt * 8 + grp;
        #pragma unroll
        for (int ks = 0; ks < 4; ks++) {
            const int k0 = ks * 16 + 2 * qd;
            wB[nt][ks] = make_uint2(
                pkh2(W2[row * 64 + k0    ], W2[row * 64 + k0 + 1]),
                pkh2(W2[row * 64 + k0 + 8], W2[row * 64 + k0 + 9]));
        }
    }

    const int e = tid >> 1, q = tid & 1;        // gather role: 2 threads/edge

    // scatter role: tid<128; warp = chain of 32 edges, lane = word (2 cols)
    const int chS = tid >> 5;          // 0..3
    const int lS  = tid & 31;
    const int r2S = chS * 32;
    float2 bv = make_float2(0.f, 0.f);
    if (tid < 128) bv = *(const float2*)&b2[lS * 2];

    const int n_tiles = (n_edges + E_TILE - 1) / E_TILE;
    const int t0 = blockIdx.x * tiles_per_block;
    const int t1 = min(t0 + tiles_per_block, n_tiles);
    if (t0 >= t1) return;   // block-uniform

    unsigned int sbase;
    asm("{ .reg .u64 t; cvta.to.shared.u64 t, %1; cvt.u32.u64 %0, t; }"
        : "=r"(sbase) : "l"((void*)usmem));
    const unsigned int lds_off0 =
        ((unsigned)((m0      + (lane & 15)) * SHH + (lane >> 4) * 4)) * 4u;
    const unsigned int lds_off1 =
        ((unsigned)((m0 + 16 + (lane & 15)) * SHH + (lane >> 4) * 4)) * 4u;

    // ---- prologue: full gather of tile t0 -> sH buf0, sDst[t0&3] ----
    {
        const int eg = t0 * E_TILE + e;
        const bool valid = (eg < n_edges);
        int s = 0, d = -1;
        if (valid) { s = g_src_s[eg]; d = g_dst_s[eg]; }
        const uint4* a4 = (const uint4*)(Ah + (size_t)(valid ? d : 0) * 32) + q * 4;
        const uint4* b4 = (const uint4*)(Bh + (size_t)s * 32) + q * 4;
        uint4* hp = (uint4*)((char*)sHb + e * (SHH * 4) + q * 64);
        if (q == 0) sDstb[(t0 & 3) * 128 + e] = d;
        #pragma unroll
        for (int v = 0; v < 4; v++) {
            uint4 a = valid ? a4[v] : make_uint4(0,0,0,0);
            uint4 b = valid ? b4[v] : make_uint4(0,0,0,0);
            uint4 hv;
            hv.x = haddrelu2(a.x, b.x);
            hv.y = haddrelu2(a.y, b.y);
            hv.z = haddrelu2(a.z, b.z);
            hv.w = haddrelu2(a.w, b.w);
            hp[v] = hv;
        }
    }
    __syncthreads();

    int p = 0;
    for (int t = t0; t < t1; t++, p ^= 1) {
        // ---- 1. prefetch next tile's random B[src] (issues before mma) ----
        const int tn = t + 1;
        const int egN = tn * E_TILE + e;
        const bool validN = (tn < t1) && (egN < n_edges);
        int sN = 0, dN = -1;
        if (validN) { sN = g_src_s[egN]; dN = g_dst_s[egN]; }
        uint4 bb[4];
        {
            const uint4* b4 = (const uint4*)(Bh + (size_t)sN * 32) + q * 4;
            #pragma unroll
            for (int v = 0; v < 4; v++)
                bb[v] = validN ? b4[v] : make_uint4(0,0,0,0);
        }

        // ---- 2. f16 mma: 2 m-groups x 4 nt x 4 ks ----
        float acc[2][4][4];
        #pragma unroll
        for (int mg = 0; mg < 2; mg++)
            #pragma unroll
            for (int nt = 0; nt < 4; nt++)
                #pragma unroll
                for (int j = 0; j < 4; j++) acc[mg][nt][j] = 0.f;

        const unsigned int pb = sbase + (unsigned)p * (SHH_WORDS * 4u);
        #pragma unroll
        for (int ks = 0; ks < 4; ks++) {
            unsigned int a0[2], a1[2], a2[2], a3[2];
            ldsm_x4(a0[0], a1[0], a2[0], a3[0], pb + lds_off0 + ks * 32u);
            ldsm_x4(a0[1], a1[1], a2[1], a3[1], pb + lds_off1 + ks * 32u);
            #pragma unroll
            for (int mg = 0; mg < 2; mg++) {
                #pragma unroll
                for (int nt = 0; nt < 4; nt++) {
                    asm volatile(
                        "mma.sync.aligned.m16n8k16.row.col.f32.f16.f16.f32 "
                        "{%0,%1,%2,%3}, {%4,%5,%6,%7}, {%8,%9}, {%0,%1,%2,%3};"
                        : "+f"(acc[mg][nt][0]), "+f"(acc[mg][nt][1]),
                          "+f"(acc[mg][nt][2]), "+f"(acc[mg][nt][3])
                        : "r"(a0[mg]), "r"(a1[mg]), "r"(a2[mg]), "r"(a3[mg]),
                          "r"(wB[nt][ks].x), "r"(wB[nt][ks].y));
                }
            }
        }

        // ---- 3. finish next-tile gather: A row (cache-hot) + fuse + STS ----
        {
            const uint4* a4 = (const uint4*)(Ah + (size_t)(validN ? dN : 0) * 32) + q * 4;
            uint4* hp = (uint4*)((char*)sHb + (p ^ 1) * (SHH_WORDS * 4)
                                 + e * (SHH * 4) + q * 64);
            if (q == 0) sDstb[(tn & 3) * 128 + e] = dN;
            #pragma unroll
            for (int v = 0; v < 4; v++) {
                uint4 a = validN ? a4[v] : make_uint4(0,0,0,0);
                uint4 hv;
                hv.x = haddrelu2(a.x, bb[v].x);
                hv.y = haddrelu2(a.y, bb[v].y);
                hv.z = haddrelu2(a.z, bb[v].z);
                hv.w = haddrelu2(a.w, bb[v].w);
                hp[v] = hv;
            }
        }

        // ---- 4. pack acc -> f16 sMsg[p] (bias added at emit) ----
        unsigned int* msg = sMsgb + p * SMH_WORDS;
        #pragma unroll
        for (int mg = 0; mg < 2; mg++) {
            const int r0 = m0 + mg * 16 + grp;
            #pragma unroll
            for (int nt = 0; nt < 4; nt++) {
                const int wc = (wid & 1) * 16 + nt * 4 + qd;
                msg[(r0    ) * SMH + wc] = pkh2(acc[mg][nt][0], acc[mg][nt][1]);
                msg[(r0 + 8) * SMH + wc] = pkh2(acc[mg][nt][2], acc[mg][nt][3]);
            }
        }
        __syncthreads();   // the ONE barrier: sMsg[p], sH[p^1], sDst ready

        // ---- 5. scatter (tid<128): chain of 32, packed hmax2, bias at emit ----
        if (tid < 128) {
            const int* sd = sDstb + (t & 3) * 128;
            int rd[32];
            #pragma unroll
            for (int i4 = 0; i4 < 8; i4++)
                *(int4*)&rd[i4 * 4] = *(const int4*)&sd[r2S + i4 * 4];

            unsigned int cur = 0;
            int prev = -2;
            #pragma unroll
            for (int h = 0; h < 4; h++) {
                unsigned int mv[8];
                #pragma unroll
                for (int j = 0; j < 8; j++)
                    mv[j] = msg[(r2S + h * 8 + j) * SMH + lS];
                #pragma unroll
                for (int j = 0; j < 8; j++) {
                    const int g = h * 8 + j;
                    const int de = rd[g];
                    cur = (de == prev) ? hmax2w(cur, mv[j]) : mv[j];
                    prev = de;
                    const bool last = (g == 31) || (rd[g + 1] != de);
                    if (last && de >= 0) {
                        __half2 hc = *reinterpret_cast<__half2*>(&cur);
                        float2 f = __half22float2(hc);
                        float* op = out + (size_t)de * DIMV + lS * 2;
                        atomic_max_float(op    , f.x + bv.x);
                        atomic_max_float(op + 1, f.y + bv.y);
                    }
                }
            }
        }
        // no trailing barrier (verified buffer rotation: sH[p] dead after the
        // barrier; sMsg[p^1] readers drained before anyone passes barrier(t);
        // sDst ring stride 2 mod 4 disjoint).
    }
}

extern "C" void kernel_launch(void* const* d_in, const int* in_sizes, int n_in,
                              void* d_out, int out_size)
{
    const float* x   = (const float*)d_in[0];
    const int*   ei  = (const int*)d_in[1];
    const float* W1a = (const float*)d_in[2];
    const float* b1a = (const float*)d_in[3];
    const float* W2a = (const float*)d_in[4];
    const float* b2a = (const float*)d_in[5];
    const float* W1b = (const float*)d_in[6];
    const float* b1b = (const float*)d_in[7];
    const float* W2b = (const float*)d_in[8];
    const float* b2b = (const float*)d_in[9];

    const int n_nodes = in_sizes[0] / DIMV;
    const int n_edges = in_sizes[1] / 2;
    const int* src = ei;
    const int* dst = ei + n_edges;

    float* out = (float*)d_out;
    float* h1;
    unsigned int *Abuf, *Bbuf;
    cudaGetSymbolAddress((void**)&h1,   g_h1);
    cudaGetSymbolAddress((void**)&Abuf, g_A);
    cudaGetSymbolAddress((void**)&Bbuf, g_B);

    cudaFuncSetAttribute(fused_spi_kernel,
                         cudaFuncAttributeMaxDynamicSharedMemorySize, PRE_SMEM_BYTES);
    cudaFuncSetAttribute(edge_kernel,
                         cudaFuncAttributeMaxDynamicSharedMemorySize, EDGE_SMEM_BYTES);

    const int n_feat = n_nodes * DIMV;
    const int init_blocks = (n_feat + TPB - 1) / TPB;
    const int pre_blocks  = (n_nodes + 63) / 64;
    const int edge_blocks = 148 * 2;
    const int eb = (n_edges + TPB - 1) / TPB;

    const int n_tiles = (n_edges + E_TILE - 1) / E_TILE;
    const int tiles_per_block = (n_tiles + edge_blocks - 1) / edge_blocks;

    // #1 histogram (g_count zeroed by previous scan / initial BSS)
    hist_kernel<<<eb, TPB>>>(dst, n_edges);
    // #2 exclusive scan + empty bitmask + re-zero counts
    scan_zero_kernel<<<1, 1024>>>(n_nodes);
    // #3 fused: scatter-sort + init(h1, bitmask) + pre(layer1)
    fused_spi_kernel<<<eb + init_blocks + pre_blocks, TPB, PRE_SMEM_BYTES>>>(
        src, dst, n_edges, x, W1a, b1a, Abuf, Bbuf, n_nodes,
        h1, n_feat, eb, init_blocks);
    // #4 edge layer 1  <-- ncu captures this launch
    edge_kernel<<<edge_blocks, TPB, EDGE_SMEM_BYTES>>>(Abuf, Bbuf, W2a, b2a,
                                                       h1, n_edges, tiles_per_block);
    // #5 fused: init(out, bitmask) + pre(layer2)
    fused_spi_kernel<<<init_blocks + pre_blocks, TPB, PRE_SMEM_BYTES>>>(
        src, dst, n_edges, h1, W1b, b1b, Abuf, Bbuf, n_nodes,
        out, n_feat, 0, init_blocks);
    // #6 edge layer 2
    edge_kernel<<<edge_blocks, TPB, EDGE_SMEM_BYTES>>>(Abuf, Bbuf, W2b, b2b,
                                                       out, n_edges, tiles_per_block);
}